// round 15
// baseline (speedup 1.0000x reference)
#include <cuda_runtime.h>
#include <cuda_fp16.h>
#include <math.h>

#define D 64
#define V_MAX 100000
#define NBMAX 128
#define E_NG_MAX  2000000
#define E_LOC_MAX 1000000
#define E_INT_MAX 1200000
#define E_SIM_MAX  800000

// ---------------- scratch ------------------------------------------------------
__device__ float   g_wL[V_MAX];
__device__ float   g_wG[V_MAX];
__device__ __half2 g_WNL[V_MAX * 32];
__device__ __half2 g_WNG[V_MAX * 32];
__device__ float   g_den[2 * V_MAX];     // [0..V): ng denom, [V_MAX..): local denom

__device__ int g_cnt[4 * V_MAX];
__device__ int g_off[4 * (V_MAX + 1)];
__device__ int g_cur[4 * V_MAX];
__device__ int g_bsum[4 * NBMAX];
__device__ int g_binNG[E_NG_MAX];
__device__ int g_binLOC[E_LOC_MAX];
__device__ int g_binI[E_INT_MAX];
__device__ int g_binS[E_SIM_MAX];

__device__ __forceinline__ float tanh_fast(float x) {
    float r;
    asm("tanh.approx.f32 %0, %1;" : "=f"(r) : "f"(x));
    return r;
}

__device__ __forceinline__ unsigned long long addf32x2(
    unsigned long long a, unsigned long long b)
{
    unsigned long long r;
    asm("add.rn.f32x2 %0, %1, %2;" : "=l"(r) : "l"(a), "l"(b));
    return r;
}

// ---------------- scores helper (interleaved float2 layout, 4 nodes/warp) ----------
__device__ __forceinline__ void score4(
    const float2* __restrict__ N2, const float* __restrict__ sW,
    const float2* __restrict__ sw2, float* __restrict__ wOut,
    __half2* __restrict__ WN, int base, int V, int lane)
{
    float2 n[4];
    #pragma unroll
    for (int i = 0; i < 4; i++) {
        int v = (base + i < V) ? base + i : V - 1;
        n[i] = N2[(size_t)v * 32 + lane];
    }
    float2 a[4] = {{0,0},{0,0},{0,0},{0,0}};
    const float2* W2 = (const float2*)sW;
    #pragma unroll
    for (int kk = 0; kk < 32; kk++) {
        float2 w0 = W2[(2 * kk) * 32 + lane];
        float2 w1 = W2[(2 * kk + 1) * 32 + lane];
        #pragma unroll
        for (int i = 0; i < 4; i++) {
            float xk0 = __shfl_sync(0xffffffffu, n[i].x, kk);
            float xk1 = __shfl_sync(0xffffffffu, n[i].y, kk);
            a[i].x += xk0 * w0.x + xk1 * w1.x;
            a[i].y += xk0 * w0.y + xk1 * w1.y;
        }
    }
    float2 w2v = sw2[lane];
    #pragma unroll
    for (int i = 0; i < 4; i++) {
        float e = tanh_fast(a[i].x) * w2v.x + tanh_fast(a[i].y) * w2v.y;
        #pragma unroll
        for (int o = 16; o > 0; o >>= 1) e += __shfl_xor_sync(0xffffffffu, e, o);
        float w = expf(e);
        int v = base + i;
        if (v < V) {
            if (lane == 0) wOut[v] = w;
            WN[(size_t)v * 32 + lane] = __float22half2_rn(make_float2(w * n[i].x, w * n[i].y));
        }
    }
}

// ---------------- phase1: fused histogram (4 graphs) + node scores -----------------
__global__ __launch_bounds__(256) void phase1_kernel(
    const int* __restrict__ d0, int e0, const int* __restrict__ d1, int e1,
    const int* __restrict__ d2, int e2, const int* __restrict__ d3, int e3, int CB,
    const float* __restrict__ localN, const float* __restrict__ globalN,
    const float* __restrict__ lW1, const float* __restrict__ lw2,
    const float* __restrict__ gW1, const float* __restrict__ gw2, int V, int SB)
{
    if ((int)blockIdx.x < CB) {
        int i = blockIdx.x * blockDim.x + threadIdx.x;
        int g, j;
        if (i < e0)                     { g = 0; j = i; }
        else if (i < e0 + e1)           { g = 1; j = i - e0; }
        else if (i < e0 + e1 + e2)      { g = 2; j = i - e0 - e1; }
        else if (i < e0 + e1 + e2 + e3) { g = 3; j = i - e0 - e1 - e2; }
        else return;
        const int* d = (g == 0) ? d0 : (g == 1) ? d1 : (g == 2) ? d2 : d3;
        atomicAdd(&g_cnt[g * V_MAX + d[j]], 1);
        return;
    }
    __shared__ float sWl[D * D];
    __shared__ float sWg[D * D];
    __shared__ float2 swl[32];
    __shared__ float2 swg[32];
    for (int i = threadIdx.x; i < D * D; i += blockDim.x) { sWl[i] = lW1[i]; sWg[i] = gW1[i]; }
    for (int i = threadIdx.x; i < 32; i += blockDim.x) {
        swl[i] = ((const float2*)lw2)[i];
        swg[i] = ((const float2*)gw2)[i];
    }
    __syncthreads();

    int lane = threadIdx.x & 31;
    int grp  = ((blockIdx.x - CB) * blockDim.x + threadIdx.x) >> 5;
    int ngrp = SB * 8;

    for (int base = grp * 4; base < V; base += ngrp * 4) {
        score4((const float2*)localN,  sWl, swl, g_wL, g_WNL, base, V, lane);
        score4((const float2*)globalN, sWg, swg, g_wG, g_WNG, base, V, lane);
    }
}

// ---------------- scan helpers (parallel 3-kernel version) -------------------------
__device__ __forceinline__ int block_incl_scan(int x, int tid, int* ws) {
    int lane = tid & 31, wid = tid >> 5;
    #pragma unroll
    for (int o = 1; o < 32; o <<= 1) {
        int y = __shfl_up_sync(0xffffffffu, x, o);
        if (lane >= o) x += y;
    }
    if (lane == 31) ws[wid] = x;
    __syncthreads();
    if (wid == 0) {
        int v = (lane < 8) ? ws[lane] : 0;
        #pragma unroll
        for (int o = 1; o < 8; o <<= 1) {
            int y = __shfl_up_sync(0xffffffffu, v, o);
            if (lane >= o) v += y;
        }
        if (lane < 8) ws[lane] = v;
    }
    __syncthreads();
    if (wid > 0) x += ws[wid - 1];
    return x;
}

__global__ __launch_bounds__(256) void scan1_kernel(int V) {
    __shared__ int ws[8];
    int g = blockIdx.y, b = blockIdx.x, tid = threadIdx.x;
    int base = b * 1024 + tid * 4;
    int s = 0;
    #pragma unroll
    for (int j = 0; j < 4; j++) { int i = base + j; if (i < V) s += g_cnt[g * V_MAX + i]; }
    int incl = block_incl_scan(s, tid, ws);
    if (tid == 255) g_bsum[g * NBMAX + b] = incl;
}

__global__ __launch_bounds__(128) void scan2_kernel(int V) {
    __shared__ int ws[8];
    int g = blockIdx.x, t = threadIdx.x;
    int x = g_bsum[g * NBMAX + t];
    int orig = x;
    int incl = block_incl_scan(x, t, ws);
    g_bsum[g * NBMAX + t] = incl - orig;
    if (t == 127) g_off[g * (V_MAX + 1) + V] = incl;
}

__global__ __launch_bounds__(256) void scan3_kernel(int V) {
    __shared__ int ws[8];
    int g = blockIdx.y, b = blockIdx.x, tid = threadIdx.x;
    int base = b * 1024 + tid * 4;
    int c[4]; int s = 0;
    #pragma unroll
    for (int j = 0; j < 4; j++) {
        int i = base + j;
        c[j] = (i < V) ? g_cnt[g * V_MAX + i] : 0;
        s += c[j];
    }
    int incl = block_incl_scan(s, tid, ws);
    int p = g_bsum[g * NBMAX + b] + incl - s;
    #pragma unroll
    for (int j = 0; j < 4; j++) {
        int i = base + j;
        if (i < V) { g_off[g * (V_MAX + 1) + i] = p; g_cur[g * V_MAX + i] = p; p += c[j]; }
    }
}

// ---------------- fused scatter over 4 graphs + GAT denominators -------------------
__global__ __launch_bounds__(256) void scatter_kernel(
    const int* __restrict__ d0, const int* __restrict__ s0, int e0,
    const int* __restrict__ d1, const int* __restrict__ s1, int e1,
    const int* __restrict__ d2, int e2,
    const int* __restrict__ d3, int e3)
{
    int i = blockIdx.x * blockDim.x + threadIdx.x;
    int g, j;
    if (i < e0)                     { g = 0; j = i; }
    else if (i < e0 + e1)           { g = 1; j = i - e0; }
    else if (i < e0 + e1 + e2)      { g = 2; j = i - e0 - e1; }
    else if (i < e0 + e1 + e2 + e3) { g = 3; j = i - e0 - e1 - e2; }
    else return;
    if (g == 0) {
        int dst = d0[j], src = s0[j];
        int p = atomicAdd(&g_cur[0 * V_MAX + dst], 1);
        g_binNG[p] = src;
        atomicAdd(&g_den[dst], __ldg(&g_wG[src]));
    } else if (g == 1) {
        int dst = d1[j], src = s1[j];
        int p = atomicAdd(&g_cur[1 * V_MAX + dst], 1);
        g_binLOC[p] = src;
        atomicAdd(&g_den[V_MAX + dst], __ldg(&g_wL[src]));
    } else if (g == 2) {
        int dst = d2[j];
        int p = atomicAdd(&g_cur[2 * V_MAX + dst], 1);
        g_binI[p] = j;
    } else {
        int dst = d3[j];
        int p = atomicAdd(&g_cur[3 * V_MAX + dst], 1);
        g_binS[p] = j;
    }
}

// ---------------- split-warp GAT gather: 2 edges per LDG ---------------------------
// Lanes 0-15 handle edge e, lanes 16-31 edge e+1. Each lane loads uint2 (4 halves =
// features 4*sl .. 4*sl+3). Result (float4, features 4*(lane&15)) valid in ALL lanes
// after the cross-half combine.
__device__ __forceinline__ float4 gat_gather_sw(
    const int* __restrict__ bin, int e, int eEnd,
    const uint2* __restrict__ WN2, int h, int sl)
{
    float4 acc  = make_float4(0.f, 0.f, 0.f, 0.f);
    float4 acc2 = make_float4(0.f, 0.f, 0.f, 0.f);
    for (; e + 4 <= eEnd; e += 4) {
        int s0 = __ldg(bin + e + h);
        int s1 = __ldg(bin + e + 2 + h);
        uint2 q0 = __ldg(WN2 + (size_t)s0 * 16 + sl);
        uint2 q1 = __ldg(WN2 + (size_t)s1 * 16 + sl);
        float2 f00 = __half22float2(*(const __half2*)&q0.x);
        float2 f01 = __half22float2(*(const __half2*)&q0.y);
        float2 f10 = __half22float2(*(const __half2*)&q1.x);
        float2 f11 = __half22float2(*(const __half2*)&q1.y);
        acc.x  += f00.x; acc.y  += f00.y; acc.z  += f01.x; acc.w  += f01.y;
        acc2.x += f10.x; acc2.y += f10.y; acc2.z += f11.x; acc2.w += f11.y;
    }
    if (e + 2 <= eEnd) {
        int s = __ldg(bin + e + h);
        uint2 q = __ldg(WN2 + (size_t)s * 16 + sl);
        float2 f0 = __half22float2(*(const __half2*)&q.x);
        float2 f1 = __half22float2(*(const __half2*)&q.y);
        acc.x += f0.x; acc.y += f0.y; acc.z += f1.x; acc.w += f1.y;
        e += 2;
    }
    if (e < eEnd && h == 0) {
        int s = __ldg(bin + e);
        uint2 q = __ldg(WN2 + (size_t)s * 16 + sl);
        float2 f0 = __half22float2(*(const __half2*)&q.x);
        float2 f1 = __half22float2(*(const __half2*)&q.y);
        acc.x += f0.x; acc.y += f0.y; acc.z += f1.x; acc.w += f1.y;
    }
    acc.x += acc2.x; acc.y += acc2.y; acc.z += acc2.z; acc.w += acc2.w;
    acc.x += __shfl_xor_sync(0xffffffffu, acc.x, 16);
    acc.y += __shfl_xor_sync(0xffffffffu, acc.y, 16);
    acc.z += __shfl_xor_sync(0xffffffffu, acc.z, 16);
    acc.w += __shfl_xor_sync(0xffffffffu, acc.w, 16);
    return acc;
}

// ---------------- split-warp mean gather: 2 edges per LDG.128 ----------------------
// fp32 row = 256B = 16 x 16B; lane loads ulonglong2 at element sl of its edge's row.
__device__ __forceinline__ float4 mean_gather_sw(
    const int* __restrict__ bin, int e, int eEnd,
    const ulonglong2* __restrict__ E16, int h, int sl)
{
    int cnt = eEnd - e;
    unsigned long long a0 = 0ull, a1 = 0ull, b0 = 0ull, b1 = 0ull;
    for (; e + 4 <= eEnd; e += 4) {
        int s0 = __ldg(bin + e + h);
        int s1 = __ldg(bin + e + 2 + h);
        ulonglong2 q0 = __ldg(E16 + (size_t)s0 * 16 + sl);
        ulonglong2 q1 = __ldg(E16 + (size_t)s1 * 16 + sl);
        a0 = addf32x2(a0, q0.x); a1 = addf32x2(a1, q0.y);
        b0 = addf32x2(b0, q1.x); b1 = addf32x2(b1, q1.y);
    }
    if (e + 2 <= eEnd) {
        int s = __ldg(bin + e + h);
        ulonglong2 q = __ldg(E16 + (size_t)s * 16 + sl);
        a0 = addf32x2(a0, q.x); a1 = addf32x2(a1, q.y);
        e += 2;
    }
    if (e < eEnd && h == 0) {
        int s = __ldg(bin + e);
        ulonglong2 q = __ldg(E16 + (size_t)s * 16 + sl);
        a0 = addf32x2(a0, q.x); a1 = addf32x2(a1, q.y);
    }
    a0 = addf32x2(a0, b0);
    a1 = addf32x2(a1, b1);
    float x, y, z, w;
    asm("mov.b64 {%0,%1}, %2;" : "=f"(x), "=f"(y) : "l"(a0));
    asm("mov.b64 {%0,%1}, %2;" : "=f"(z), "=f"(w) : "l"(a1));
    x += __shfl_xor_sync(0xffffffffu, x, 16);
    y += __shfl_xor_sync(0xffffffffu, y, 16);
    z += __shfl_xor_sync(0xffffffffu, z, 16);
    w += __shfl_xor_sync(0xffffffffu, w, 16);
    float inv = cnt > 0 ? 1.f / (float)cnt : 1.f;
    return make_float4(x * inv, y * inv, z * inv, w * inv);
}

// Redistribute float4 (features 4*(lane&15), valid in all lanes) to float2-per-lane
// layout (lane l holds features 2l, 2l+1).
__device__ __forceinline__ float2 redist(float4 a, int lane) {
    int src = lane >> 1;
    float x0 = __shfl_sync(0xffffffffu, a.x, src);
    float x1 = __shfl_sync(0xffffffffu, a.y, src);
    float x2 = __shfl_sync(0xffffffffu, a.z, src);
    float x3 = __shfl_sync(0xffffffffu, a.w, src);
    return (lane & 1) ? make_float2(x2, x3) : make_float2(x0, x1);
}

// ---------------- mega node kernel: 1 node per warp, split-warp gathers -------------
__global__ __launch_bounds__(256, 6) void node_kernel(
    float* __restrict__ out, const float* __restrict__ edge_E, int E_INT,
    const float* __restrict__ Ws,
    const float* __restrict__ eW1, const float* __restrict__ ew2,
    const float* __restrict__ eW3, int V)
{
    __shared__ float sW1[D * D];
    __shared__ float sW3[D * D];
    __shared__ float2 sw2[32];
    for (int i = threadIdx.x; i < D * D; i += blockDim.x) { sW1[i] = eW1[i]; sW3[i] = eW3[i]; }
    for (int i = threadIdx.x; i < 32; i += blockDim.x) sw2[i] = ((const float2*)ew2)[i];
    __syncthreads();

    int v    = (blockIdx.x * blockDim.x + threadIdx.x) >> 5;
    int lane = threadIdx.x & 31;
    if (v >= V) return;
    int h  = lane >> 4;
    int sl = lane & 15;

    const int* offNG  = g_off + 0 * (V_MAX + 1);
    const int* offLOC = g_off + 1 * (V_MAX + 1);
    const int* offI   = g_off + 2 * (V_MAX + 1);
    const int* offS   = g_off + 3 * (V_MAX + 1);

    // local GAT -> out[:, 0:64] (direct float4 write from lanes 0-15)
    {
        float4 lacc = gat_gather_sw(g_binLOC, offLOC[v], offLOC[v + 1],
                                    (const uint2*)g_WNL, h, sl);
        float d = g_den[V_MAX + v];
        float inv = d > 0.f ? 1.f / d : 1.f;
        if (h == 0) {
            float4* out4 = (float4*)out;
            out4[(size_t)v * 32 + sl] =
                make_float4(lacc.x * inv, lacc.y * inv, lacc.z * inv, lacc.w * inv);
        }
    }

    // ng GAT
    float2 np;
    {
        float4 s4 = gat_gather_sw(g_binNG, offNG[v], offNG[v + 1],
                                  (const uint2*)g_WNG, h, sl);
        float d = g_den[v];
        float inv = d > 0.f ? 1.f / d : 1.f;
        float2 r = redist(s4, lane);
        np = make_float2(r.x * inv, r.y * inv);
    }

    // means
    float2 yi, ys;
    {
        float4 yi4 = mean_gather_sw(g_binI, offI[v], offI[v + 1],
                                    (const ulonglong2*)edge_E, h, sl);
        float4 ys4 = mean_gather_sw(g_binS, offS[v], offS[v + 1],
                                    (const ulonglong2*)(edge_E + (size_t)E_INT * D), h, sl);
        yi = redist(yi4, lane);
        ys = redist(ys4, lane);
    }

    const float2* W1_2 = (const float2*)sW1;
    const float2* W3_2 = (const float2*)sW3;

    // a = yi @ eW1, b = ys @ eW1
    float2 a = make_float2(0.f, 0.f), b = make_float2(0.f, 0.f);
    #pragma unroll
    for (int kk = 0; kk < 32; kk++) {
        float2 w0 = W1_2[(2 * kk) * 32 + lane];
        float2 w1 = W1_2[(2 * kk + 1) * 32 + lane];
        float yi0 = __shfl_sync(0xffffffffu, yi.x, kk);
        float yi1 = __shfl_sync(0xffffffffu, yi.y, kk);
        float ys0 = __shfl_sync(0xffffffffu, ys.x, kk);
        float ys1 = __shfl_sync(0xffffffffu, ys.y, kk);
        a.x += yi0 * w0.x + yi1 * w1.x;
        a.y += yi0 * w0.y + yi1 * w1.y;
        b.x += ys0 * w0.x + ys1 * w1.x;
        b.y += ys0 * w0.y + ys1 * w1.y;
    }
    float2 w2v = sw2[lane];
    float eI = tanhf(a.x) * w2v.x + tanhf(a.y) * w2v.y;
    float eS = tanhf(b.x) * w2v.x + tanhf(b.y) * w2v.y;
    #pragma unroll
    for (int o = 16; o > 0; o >>= 1) {
        eI += __shfl_xor_sync(0xffffffffu, eI, o);
        eS += __shfl_xor_sync(0xffffffffu, eS, o);
    }
    float mx = fmaxf(eI, eS);
    float u0 = expf(eI - mx), u1 = expf(eS - mx);
    float invu = 1.f / (u0 + u1);
    float A0 = u0 * invu, A1 = u1 * invu;
    float2 oy = make_float2(A0 * yi.x + A1 * ys.x, A0 * yi.y + A1 * ys.y);

    // Fg = oy @ eW3
    float2 f = make_float2(0.f, 0.f);
    #pragma unroll
    for (int kk = 0; kk < 32; kk++) {
        float2 w0 = W3_2[(2 * kk) * 32 + lane];
        float2 w1 = W3_2[(2 * kk + 1) * 32 + lane];
        float o0 = __shfl_sync(0xffffffffu, oy.x, kk);
        float o1 = __shfl_sync(0xffffffffu, oy.y, kk);
        f.x += o0 * w0.x + o1 * w1.x;
        f.y += o0 * w0.y + o1 * w1.y;
    }

    float2 wsv = ((const float2*)Ws)[(size_t)v * 32 + lane];
    float2* out2 = (float2*)out;
    out2[(size_t)v * 64 + 32 + lane] =
        make_float2(wsv.x * f.x + np.x, wsv.y * f.y + np.y);
}

// ---------------- launch ---------------------------------------------------------
extern "C" void kernel_launch(void* const* d_in, const int* in_sizes, int n_in,
                              void* d_out, int out_size)
{
    const float* local_N  = (const float*)d_in[0];
    const float* global_N = (const float*)d_in[1];
    const float* edge_E   = (const float*)d_in[2];
    const float* Ws       = (const float*)d_in[3];
    const float* lW1      = (const float*)d_in[4];
    const float* lw2      = (const float*)d_in[5];
    const float* gW1      = (const float*)d_in[6];
    const float* gw2      = (const float*)d_in[7];
    const float* eW1      = (const float*)d_in[8];
    const float* ew2      = (const float*)d_in[9];
    const float* eW3      = (const float*)d_in[10];
    const int* ng_src     = (const int*)d_in[11];
    const int* ng_dst     = (const int*)d_in[12];
    const int* local_src  = (const int*)d_in[13];
    const int* local_dst  = (const int*)d_in[14];
    const int* int_dst    = (const int*)d_in[16];
    const int* sim_dst    = (const int*)d_in[18];

    const int V      = in_sizes[0] / D;
    const int E_NG   = in_sizes[11];
    const int E_LOC  = in_sizes[13];
    const int E_INT  = in_sizes[15];
    const int E_SIM  = in_sizes[17];
    const int E_ALL  = E_NG + E_LOC + E_INT + E_SIM;

    float* out = (float*)d_out;

    int* pCnt;
    float* pDen;
    cudaGetSymbolAddress((void**)&pCnt, g_cnt);
    cudaGetSymbolAddress((void**)&pDen, g_den);
    cudaMemsetAsync(pCnt, 0, 4 * V_MAX * sizeof(int));
    cudaMemsetAsync(pDen, 0, 2 * V_MAX * sizeof(float));

    // phase1: fused count + scores
    int CB = (E_ALL + 255) / 256;
    int SB = (V + 31) / 32;
    phase1_kernel<<<CB + SB, 256>>>(ng_dst, E_NG, local_dst, E_LOC,
                                    int_dst, E_INT, sim_dst, E_SIM, CB,
                                    local_N, global_N, lW1, lw2, gW1, gw2, V, SB);

    // parallel scans
    dim3 sgrid(NBMAX, 4);
    scan1_kernel<<<sgrid, 256>>>(V);
    scan2_kernel<<<4, 128>>>(V);
    scan3_kernel<<<sgrid, 256>>>(V);

    // scatter (+ GAT denominators via scalar atomics)
    scatter_kernel<<<(E_ALL + 255) / 256, 256>>>(ng_dst, ng_src, E_NG,
                                                 local_dst, local_src, E_LOC,
                                                 int_dst, E_INT, sim_dst, E_SIM);

    // fused per-node gathers + attention + output
    node_kernel<<<(V * 32 + 255) / 256, 256>>>(out, edge_E, E_INT, Ws, eW1, ew2, eW3, V);
}

// round 16
// speedup vs baseline: 1.0591x; 1.0591x over previous
#include <cuda_runtime.h>
#include <cuda_fp16.h>
#include <math.h>

#define D 64
#define V_MAX 100000
#define NBMAX 128
#define E_NG_MAX  2000000
#define E_LOC_MAX 1000000
#define E_INT_MAX 1200000
#define E_SIM_MAX  800000

// ---------------- scratch ------------------------------------------------------
__device__ float   g_wL[V_MAX];
__device__ float   g_wG[V_MAX];
__device__ __half2 g_WNL[V_MAX * 32];
__device__ __half2 g_WNG[V_MAX * 32];
__device__ float   g_den[2 * V_MAX];     // [0..V): ng denom, [V_MAX..): local denom

__device__ int g_cnt[4 * V_MAX];
__device__ int g_off[4 * (V_MAX + 1)];
__device__ int g_cur[4 * V_MAX];
__device__ int g_bsum[4 * NBMAX];
__device__ int g_binNG[E_NG_MAX];
__device__ int g_binLOC[E_LOC_MAX];
__device__ int g_binI[E_INT_MAX];
__device__ int g_binS[E_SIM_MAX];

__device__ __forceinline__ float tanh_fast(float x) {
    float r;
    asm("tanh.approx.f32 %0, %1;" : "=f"(r) : "f"(x));
    return r;
}

// Packed f32x2 add (Blackwell): one instruction for two fp32 adds.
__device__ __forceinline__ unsigned long long addf32x2(
    unsigned long long a, unsigned long long b)
{
    unsigned long long r;
    asm("add.rn.f32x2 %0, %1, %2;" : "=l"(r) : "l"(a), "l"(b));
    return r;
}

// ---------------- scores helper (interleaved float2 layout, 4 nodes/warp) ----------
__device__ __forceinline__ void score4(
    const float2* __restrict__ N2, const float* __restrict__ sW,
    const float2* __restrict__ sw2, float* __restrict__ wOut,
    __half2* __restrict__ WN, int base, int V, int lane)
{
    float2 n[4];
    #pragma unroll
    for (int i = 0; i < 4; i++) {
        int v = (base + i < V) ? base + i : V - 1;
        n[i] = N2[(size_t)v * 32 + lane];
    }
    float2 a[4] = {{0,0},{0,0},{0,0},{0,0}};
    const float2* W2 = (const float2*)sW;
    #pragma unroll
    for (int kk = 0; kk < 32; kk++) {
        float2 w0 = W2[(2 * kk) * 32 + lane];
        float2 w1 = W2[(2 * kk + 1) * 32 + lane];
        #pragma unroll
        for (int i = 0; i < 4; i++) {
            float xk0 = __shfl_sync(0xffffffffu, n[i].x, kk);
            float xk1 = __shfl_sync(0xffffffffu, n[i].y, kk);
            a[i].x += xk0 * w0.x + xk1 * w1.x;
            a[i].y += xk0 * w0.y + xk1 * w1.y;
        }
    }
    float2 w2v = sw2[lane];
    #pragma unroll
    for (int i = 0; i < 4; i++) {
        float e = tanh_fast(a[i].x) * w2v.x + tanh_fast(a[i].y) * w2v.y;
        #pragma unroll
        for (int o = 16; o > 0; o >>= 1) e += __shfl_xor_sync(0xffffffffu, e, o);
        float w = expf(e);
        int v = base + i;
        if (v < V) {
            if (lane == 0) wOut[v] = w;
            WN[(size_t)v * 32 + lane] = __float22half2_rn(make_float2(w * n[i].x, w * n[i].y));
        }
    }
}

// ---------------- phase1: fused histogram (4 graphs) + node scores -----------------
__global__ __launch_bounds__(256) void phase1_kernel(
    const int* __restrict__ d0, int e0, const int* __restrict__ d1, int e1,
    const int* __restrict__ d2, int e2, const int* __restrict__ d3, int e3, int CB,
    const float* __restrict__ localN, const float* __restrict__ globalN,
    const float* __restrict__ lW1, const float* __restrict__ lw2,
    const float* __restrict__ gW1, const float* __restrict__ gw2, int V, int SB)
{
    if ((int)blockIdx.x < CB) {
        int i = blockIdx.x * blockDim.x + threadIdx.x;
        int g, j;
        if (i < e0)                     { g = 0; j = i; }
        else if (i < e0 + e1)           { g = 1; j = i - e0; }
        else if (i < e0 + e1 + e2)      { g = 2; j = i - e0 - e1; }
        else if (i < e0 + e1 + e2 + e3) { g = 3; j = i - e0 - e1 - e2; }
        else return;
        const int* d = (g == 0) ? d0 : (g == 1) ? d1 : (g == 2) ? d2 : d3;
        atomicAdd(&g_cnt[g * V_MAX + d[j]], 1);
        return;
    }
    __shared__ float sWl[D * D];
    __shared__ float sWg[D * D];
    __shared__ float2 swl[32];
    __shared__ float2 swg[32];
    for (int i = threadIdx.x; i < D * D; i += blockDim.x) { sWl[i] = lW1[i]; sWg[i] = gW1[i]; }
    for (int i = threadIdx.x; i < 32; i += blockDim.x) {
        swl[i] = ((const float2*)lw2)[i];
        swg[i] = ((const float2*)gw2)[i];
    }
    __syncthreads();

    int lane = threadIdx.x & 31;
    int grp  = ((blockIdx.x - CB) * blockDim.x + threadIdx.x) >> 5;
    int ngrp = SB * 8;

    for (int base = grp * 4; base < V; base += ngrp * 4) {
        score4((const float2*)localN,  sWl, swl, g_wL, g_WNL, base, V, lane);
        score4((const float2*)globalN, sWg, swg, g_wG, g_WNG, base, V, lane);
    }
}

// ---------------- scan helpers (parallel 3-kernel version) -------------------------
__device__ __forceinline__ int block_incl_scan(int x, int tid, int* ws) {
    int lane = tid & 31, wid = tid >> 5;
    #pragma unroll
    for (int o = 1; o < 32; o <<= 1) {
        int y = __shfl_up_sync(0xffffffffu, x, o);
        if (lane >= o) x += y;
    }
    if (lane == 31) ws[wid] = x;
    __syncthreads();
    if (wid == 0) {
        int v = (lane < 8) ? ws[lane] : 0;
        #pragma unroll
        for (int o = 1; o < 8; o <<= 1) {
            int y = __shfl_up_sync(0xffffffffu, v, o);
            if (lane >= o) v += y;
        }
        if (lane < 8) ws[lane] = v;
    }
    __syncthreads();
    if (wid > 0) x += ws[wid - 1];
    return x;
}

__global__ __launch_bounds__(256) void scan1_kernel(int V) {
    __shared__ int ws[8];
    int g = blockIdx.y, b = blockIdx.x, tid = threadIdx.x;
    int base = b * 1024 + tid * 4;
    int s = 0;
    #pragma unroll
    for (int j = 0; j < 4; j++) { int i = base + j; if (i < V) s += g_cnt[g * V_MAX + i]; }
    int incl = block_incl_scan(s, tid, ws);
    if (tid == 255) g_bsum[g * NBMAX + b] = incl;
}

__global__ __launch_bounds__(128) void scan2_kernel(int V) {
    __shared__ int ws[8];
    int g = blockIdx.x, t = threadIdx.x;
    int x = g_bsum[g * NBMAX + t];
    int orig = x;
    int incl = block_incl_scan(x, t, ws);
    g_bsum[g * NBMAX + t] = incl - orig;
    if (t == 127) g_off[g * (V_MAX + 1) + V] = incl;
}

__global__ __launch_bounds__(256) void scan3_kernel(int V) {
    __shared__ int ws[8];
    int g = blockIdx.y, b = blockIdx.x, tid = threadIdx.x;
    int base = b * 1024 + tid * 4;
    int c[4]; int s = 0;
    #pragma unroll
    for (int j = 0; j < 4; j++) {
        int i = base + j;
        c[j] = (i < V) ? g_cnt[g * V_MAX + i] : 0;
        s += c[j];
    }
    int incl = block_incl_scan(s, tid, ws);
    int p = g_bsum[g * NBMAX + b] + incl - s;
    #pragma unroll
    for (int j = 0; j < 4; j++) {
        int i = base + j;
        if (i < V) { g_off[g * (V_MAX + 1) + i] = p; g_cur[g * V_MAX + i] = p; p += c[j]; }
    }
}

// ---------------- fused scatter over 4 graphs + GAT denominators -------------------
__global__ __launch_bounds__(256) void scatter_kernel(
    const int* __restrict__ d0, const int* __restrict__ s0, int e0,
    const int* __restrict__ d1, const int* __restrict__ s1, int e1,
    const int* __restrict__ d2, int e2,
    const int* __restrict__ d3, int e3)
{
    int i = blockIdx.x * blockDim.x + threadIdx.x;
    int g, j;
    if (i < e0)                     { g = 0; j = i; }
    else if (i < e0 + e1)           { g = 1; j = i - e0; }
    else if (i < e0 + e1 + e2)      { g = 2; j = i - e0 - e1; }
    else if (i < e0 + e1 + e2 + e3) { g = 3; j = i - e0 - e1 - e2; }
    else return;
    if (g == 0) {
        int dst = d0[j], src = s0[j];
        int p = atomicAdd(&g_cur[0 * V_MAX + dst], 1);
        g_binNG[p] = src;
        atomicAdd(&g_den[dst], __ldg(&g_wG[src]));
    } else if (g == 1) {
        int dst = d1[j], src = s1[j];
        int p = atomicAdd(&g_cur[1 * V_MAX + dst], 1);
        g_binLOC[p] = src;
        atomicAdd(&g_den[V_MAX + dst], __ldg(&g_wL[src]));
    } else if (g == 2) {
        int dst = d2[j];
        int p = atomicAdd(&g_cur[2 * V_MAX + dst], 1);
        g_binI[p] = j;
    } else {
        int dst = d3[j];
        int p = atomicAdd(&g_cur[3 * V_MAX + dst], 1);
        g_binS[p] = j;
    }
}

// ---------------- dual-node GAT gather: sums only (denoms precomputed) -------------
__device__ __forceinline__ void gat_gather2(
    const int* __restrict__ bin, int eA, int endA, int eB, int endB,
    const __half2* __restrict__ WN, int lane, float2& sumA, float2& sumB)
{
    float axA = 0.f, ayA = 0.f, axB = 0.f, ayB = 0.f;
    while (eA + 2 <= endA && eB + 2 <= endB) {
        int sA0 = bin[eA], sA1 = bin[eA + 1];
        int sB0 = bin[eB], sB1 = bin[eB + 1];
        float2 xA0 = __half22float2(__ldg(WN + (size_t)sA0 * 32 + lane));
        float2 xB0 = __half22float2(__ldg(WN + (size_t)sB0 * 32 + lane));
        float2 xA1 = __half22float2(__ldg(WN + (size_t)sA1 * 32 + lane));
        float2 xB1 = __half22float2(__ldg(WN + (size_t)sB1 * 32 + lane));
        axA += xA0.x + xA1.x; ayA += xA0.y + xA1.y;
        axB += xB0.x + xB1.x; ayB += xB0.y + xB1.y;
        eA += 2; eB += 2;
    }
    while (eA + 2 <= endA) {
        int s0 = bin[eA], s1 = bin[eA + 1];
        float2 x0 = __half22float2(__ldg(WN + (size_t)s0 * 32 + lane));
        float2 x1 = __half22float2(__ldg(WN + (size_t)s1 * 32 + lane));
        axA += x0.x + x1.x; ayA += x0.y + x1.y;
        eA += 2;
    }
    while (eB + 2 <= endB) {
        int s0 = bin[eB], s1 = bin[eB + 1];
        float2 x0 = __half22float2(__ldg(WN + (size_t)s0 * 32 + lane));
        float2 x1 = __half22float2(__ldg(WN + (size_t)s1 * 32 + lane));
        axB += x0.x + x1.x; ayB += x0.y + x1.y;
        eB += 2;
    }
    if (eA < endA) {
        float2 x = __half22float2(__ldg(WN + (size_t)bin[eA] * 32 + lane));
        axA += x.x; ayA += x.y;
    }
    if (eB < endB) {
        float2 x = __half22float2(__ldg(WN + (size_t)bin[eB] * 32 + lane));
        axB += x.x; ayB += x.y;
    }
    sumA = make_float2(axA, ayA);
    sumB = make_float2(axB, ayB);
}

// ---------------- dual-node mean gather, 4 edges/chain in flight -------------------
__device__ __forceinline__ void mean_gather2(
    const int* __restrict__ bin, int eA, int endA, int eB, int endB,
    const unsigned long long* __restrict__ E8, int lane, float2& accA, float2& accB)
{
    int cA = endA - eA, cB = endB - eB;
    unsigned long long aA0 = 0ull, aA1 = 0ull, aB0 = 0ull, aB1 = 0ull;
    // deep main loop: 4 edges per chain -> 8 independent row loads in flight
    while (eA + 4 <= endA && eB + 4 <= endB) {
        int iA0 = bin[eA],     iA1 = bin[eA + 1], iA2 = bin[eA + 2], iA3 = bin[eA + 3];
        int iB0 = bin[eB],     iB1 = bin[eB + 1], iB2 = bin[eB + 2], iB3 = bin[eB + 3];
        unsigned long long xA0 = __ldg(E8 + (size_t)iA0 * 32 + lane);
        unsigned long long xB0 = __ldg(E8 + (size_t)iB0 * 32 + lane);
        unsigned long long xA1 = __ldg(E8 + (size_t)iA1 * 32 + lane);
        unsigned long long xB1 = __ldg(E8 + (size_t)iB1 * 32 + lane);
        unsigned long long xA2 = __ldg(E8 + (size_t)iA2 * 32 + lane);
        unsigned long long xB2 = __ldg(E8 + (size_t)iB2 * 32 + lane);
        unsigned long long xA3 = __ldg(E8 + (size_t)iA3 * 32 + lane);
        unsigned long long xB3 = __ldg(E8 + (size_t)iB3 * 32 + lane);
        aA0 = addf32x2(aA0, xA0); aA1 = addf32x2(aA1, xA1);
        aA0 = addf32x2(aA0, xA2); aA1 = addf32x2(aA1, xA3);
        aB0 = addf32x2(aB0, xB0); aB1 = addf32x2(aB1, xB1);
        aB0 = addf32x2(aB0, xB2); aB1 = addf32x2(aB1, xB3);
        eA += 4; eB += 4;
    }
    // 2-wide remainders
    while (eA + 2 <= endA) {
        unsigned long long x0 = __ldg(E8 + (size_t)bin[eA] * 32 + lane);
        unsigned long long x1 = __ldg(E8 + (size_t)bin[eA + 1] * 32 + lane);
        aA0 = addf32x2(aA0, x0); aA1 = addf32x2(aA1, x1);
        eA += 2;
    }
    while (eB + 2 <= endB) {
        unsigned long long x0 = __ldg(E8 + (size_t)bin[eB] * 32 + lane);
        unsigned long long x1 = __ldg(E8 + (size_t)bin[eB + 1] * 32 + lane);
        aB0 = addf32x2(aB0, x0); aB1 = addf32x2(aB1, x1);
        eB += 2;
    }
    if (eA < endA) aA0 = addf32x2(aA0, __ldg(E8 + (size_t)bin[eA] * 32 + lane));
    if (eB < endB) aB0 = addf32x2(aB0, __ldg(E8 + (size_t)bin[eB] * 32 + lane));
    aA0 = addf32x2(aA0, aA1);
    aB0 = addf32x2(aB0, aB1);
    float ax, ay, bx, by;
    asm("mov.b64 {%0,%1}, %2;" : "=f"(ax), "=f"(ay) : "l"(aA0));
    asm("mov.b64 {%0,%1}, %2;" : "=f"(bx), "=f"(by) : "l"(aB0));
    float iA = cA > 0 ? 1.f / (float)cA : 1.f;
    float iB = cB > 0 ? 1.f / (float)cB : 1.f;
    accA = make_float2(ax * iA, ay * iA);
    accB = make_float2(bx * iB, by * iB);
}

// ---------------- mega node kernel: 2 nodes per warp, 6 blocks/SM -------------------
__global__ __launch_bounds__(256, 6) void node_kernel(
    float* __restrict__ out, const float* __restrict__ edge_E, int E_INT,
    const float* __restrict__ Ws,
    const float* __restrict__ eW1, const float* __restrict__ ew2,
    const float* __restrict__ eW3, int V)
{
    __shared__ float sW1[D * D];
    __shared__ float sW3[D * D];
    __shared__ float2 sw2[32];
    for (int i = threadIdx.x; i < D * D; i += blockDim.x) { sW1[i] = eW1[i]; sW3[i] = eW3[i]; }
    for (int i = threadIdx.x; i < 32; i += blockDim.x) sw2[i] = ((const float2*)ew2)[i];
    __syncthreads();

    int pair = (blockIdx.x * blockDim.x + threadIdx.x) >> 5;
    int lane = threadIdx.x & 31;
    int v0 = pair * 2;
    if (v0 >= V) return;
    int v1 = v0 + 1;
    bool hasB = v1 < V;
    int v1c = hasB ? v1 : v0;

    const int* offNG  = g_off + 0 * (V_MAX + 1);
    const int* offLOC = g_off + 1 * (V_MAX + 1);
    const int* offI   = g_off + 2 * (V_MAX + 1);
    const int* offS   = g_off + 3 * (V_MAX + 1);

    float2* out2 = (float2*)out;
    const float2* W1_2 = (const float2*)sW1;
    const float2* W3_2 = (const float2*)sW3;

    // local GAT -> out[:, 0:64]
    {
        float2 lA, lB;
        gat_gather2(g_binLOC, offLOC[v0], offLOC[v0 + 1], offLOC[v1c], offLOC[v1c + 1],
                    g_WNL, lane, lA, lB);
        float dA = g_den[V_MAX + v0];
        float iA = dA > 0.f ? 1.f / dA : 1.f;
        out2[(size_t)v0 * 64 + lane] = make_float2(lA.x * iA, lA.y * iA);
        if (hasB) {
            float dB = g_den[V_MAX + v1];
            float iB = dB > 0.f ? 1.f / dB : 1.f;
            out2[(size_t)v1 * 64 + lane] = make_float2(lB.x * iB, lB.y * iB);
        }
    }

    // ng GAT
    float2 np[2];
    {
        float2 sA, sB;
        gat_gather2(g_binNG, offNG[v0], offNG[v0 + 1], offNG[v1c], offNG[v1c + 1],
                    g_WNG, lane, sA, sB);
        float dA = g_den[v0];
        float iA = dA > 0.f ? 1.f / dA : 1.f;
        np[0] = make_float2(sA.x * iA, sA.y * iA);
        float dB = g_den[v1c];
        float iB = dB > 0.f ? 1.f / dB : 1.f;
        np[1] = make_float2(sB.x * iB, sB.y * iB);
    }

    // means (packed f32x2 accumulation, deep MLP)
    float2 yi[2], ys[2];
    mean_gather2(g_binI, offI[v0], offI[v0 + 1], offI[v1c], offI[v1c + 1],
                 (const unsigned long long*)edge_E, lane, yi[0], yi[1]);
    mean_gather2(g_binS, offS[v0], offS[v0 + 1], offS[v1c], offS[v1c + 1],
                 (const unsigned long long*)(edge_E + (size_t)E_INT * D), lane, ys[0], ys[1]);

    // attention matvecs, both nodes sharing weight loads
    float2 a[2] = {{0,0},{0,0}}, b[2] = {{0,0},{0,0}};
    #pragma unroll
    for (int kk = 0; kk < 32; kk++) {
        float2 w0 = W1_2[(2 * kk) * 32 + lane];
        float2 w1 = W1_2[(2 * kk + 1) * 32 + lane];
        #pragma unroll
        for (int i = 0; i < 2; i++) {
            float yi0 = __shfl_sync(0xffffffffu, yi[i].x, kk);
            float yi1 = __shfl_sync(0xffffffffu, yi[i].y, kk);
            float ys0 = __shfl_sync(0xffffffffu, ys[i].x, kk);
            float ys1 = __shfl_sync(0xffffffffu, ys[i].y, kk);
            a[i].x += yi0 * w0.x + yi1 * w1.x;
            a[i].y += yi0 * w0.y + yi1 * w1.y;
            b[i].x += ys0 * w0.x + ys1 * w1.x;
            b[i].y += ys0 * w0.y + ys1 * w1.y;
        }
    }
    float2 w2v = sw2[lane];
    float2 oy[2];
    #pragma unroll
    for (int i = 0; i < 2; i++) {
        float eI = tanhf(a[i].x) * w2v.x + tanhf(a[i].y) * w2v.y;
        float eS = tanhf(b[i].x) * w2v.x + tanhf(b[i].y) * w2v.y;
        #pragma unroll
        for (int o = 16; o > 0; o >>= 1) {
            eI += __shfl_xor_sync(0xffffffffu, eI, o);
            eS += __shfl_xor_sync(0xffffffffu, eS, o);
        }
        float mx = fmaxf(eI, eS);
        float u0 = expf(eI - mx), u1 = expf(eS - mx);
        float inv = 1.f / (u0 + u1);
        oy[i] = make_float2(u0 * inv * yi[i].x + u1 * inv * ys[i].x,
                            u0 * inv * yi[i].y + u1 * inv * ys[i].y);
    }

    float2 f[2] = {{0,0},{0,0}};
    #pragma unroll
    for (int kk = 0; kk < 32; kk++) {
        float2 w0 = W3_2[(2 * kk) * 32 + lane];
        float2 w1 = W3_2[(2 * kk + 1) * 32 + lane];
        #pragma unroll
        for (int i = 0; i < 2; i++) {
            float o0 = __shfl_sync(0xffffffffu, oy[i].x, kk);
            float o1 = __shfl_sync(0xffffffffu, oy[i].y, kk);
            f[i].x += o0 * w0.x + o1 * w1.x;
            f[i].y += o0 * w0.y + o1 * w1.y;
        }
    }

    {
        float2 wsv = ((const float2*)Ws)[(size_t)v0 * 32 + lane];
        out2[(size_t)v0 * 64 + 32 + lane] =
            make_float2(wsv.x * f[0].x + np[0].x, wsv.y * f[0].y + np[0].y);
    }
    if (hasB) {
        float2 wsv = ((const float2*)Ws)[(size_t)v1 * 32 + lane];
        out2[(size_t)v1 * 64 + 32 + lane] =
            make_float2(wsv.x * f[1].x + np[1].x, wsv.y * f[1].y + np[1].y);
    }
}

// ---------------- launch ---------------------------------------------------------
extern "C" void kernel_launch(void* const* d_in, const int* in_sizes, int n_in,
                              void* d_out, int out_size)
{
    const float* local_N  = (const float*)d_in[0];
    const float* global_N = (const float*)d_in[1];
    const float* edge_E   = (const float*)d_in[2];
    const float* Ws       = (const float*)d_in[3];
    const float* lW1      = (const float*)d_in[4];
    const float* lw2      = (const float*)d_in[5];
    const float* gW1      = (const float*)d_in[6];
    const float* gw2      = (const float*)d_in[7];
    const float* eW1      = (const float*)d_in[8];
    const float* ew2      = (const float*)d_in[9];
    const float* eW3      = (const float*)d_in[10];
    const int* ng_src     = (const int*)d_in[11];
    const int* ng_dst     = (const int*)d_in[12];
    const int* local_src  = (const int*)d_in[13];
    const int* local_dst  = (const int*)d_in[14];
    const int* int_dst    = (const int*)d_in[16];
    const int* sim_dst    = (const int*)d_in[18];

    const int V      = in_sizes[0] / D;
    const int E_NG   = in_sizes[11];
    const int E_LOC  = in_sizes[13];
    const int E_INT  = in_sizes[15];
    const int E_SIM  = in_sizes[17];
    const int E_ALL  = E_NG + E_LOC + E_INT + E_SIM;

    float* out = (float*)d_out;

    int* pCnt;
    float* pDen;
    cudaGetSymbolAddress((void**)&pCnt, g_cnt);
    cudaGetSymbolAddress((void**)&pDen, g_den);
    cudaMemsetAsync(pCnt, 0, 4 * V_MAX * sizeof(int));
    cudaMemsetAsync(pDen, 0, 2 * V_MAX * sizeof(float));

    // phase1: fused count + scores
    int CB = (E_ALL + 255) / 256;
    int SB = (V + 31) / 32;
    phase1_kernel<<<CB + SB, 256>>>(ng_dst, E_NG, local_dst, E_LOC,
                                    int_dst, E_INT, sim_dst, E_SIM, CB,
                                    local_N, global_N, lW1, lw2, gW1, gw2, V, SB);

    // parallel scans
    dim3 sgrid(NBMAX, 4);
    scan1_kernel<<<sgrid, 256>>>(V);
    scan2_kernel<<<4, 128>>>(V);
    scan3_kernel<<<sgrid, 256>>>(V);

    // scatter (+ GAT denominators via scalar atomics)
    scatter_kernel<<<(E_ALL + 255) / 256, 256>>>(ng_dst, ng_src, E_NG,
                                                 local_dst, local_src, E_LOC,
                                                 int_dst, E_INT, sim_dst, E_SIM);

    // fused per-node-pair gathers + attention + output
    int pairs = (V + 1) / 2;
    node_kernel<<<(pairs * 32 + 255) / 256, 256>>>(out, edge_E, E_INT, Ws, eW1, ew2, eW3, V);
}